// round 14
// baseline (speedup 1.0000x reference)
#include <cuda_runtime.h>
#include <cuda_fp16.h>
#include <cstdint>

#define N_NODES 50000
#define HID 128
#define LATENT 64
#define N_GRAPHS 256
#define BN_EPS 1e-5f
#define SCAN_BLOCKS 196          // 196*256 >= 50000
#define GEMM_BLOCKS 391          // ceil(50000/128)

#define A_PITCH 20               // uints per A smem row -> ldmatrix conflict-free
#define B_PITCH 20               // uints per B^T smem row -> ldmatrix conflict-free

// dynamic smem layout per buffer (bytes)
#define SM_AHI 0
#define SM_ALO 10240             // 128*20*4
#define SM_BHI 20480
#define SM_BLO 30720
#define SM_BUF 40960
#define SM_TOTAL (2 * SM_BUF)

#define W_ELEMS (3 * 128 * 128)  // fused weight image elements (uint-packed, B^T [n][k2])

// ---------------- device scratch (static, no allocation) ----------------
__device__ float g_hf32[N_NODES * HID];           // fp32 h (layer 2 only, for pool)
__device__ float g_tmp[N_NODES * HID];            // hin @ Wr partial (fp32)
__device__ int   g_deg[N_NODES];
__device__ int   g_rowstart[N_NODES + 1];
__device__ int   g_cursor[N_NODES];
__device__ int   g_csr[800000 * 2];
__device__ int   g_blocksum[SCAN_BLOCKS];
__device__ int   g_blockoff[SCAN_BLOCKS];
__device__ float g_pooled[N_GRAPHS * HID];
__device__ float g_scale[HID];
__device__ float g_shift[HID];
// fp16x2-packed hi/lo images (64 uints per 128-ch row)
__device__ unsigned int g_gahi[N_NODES * 64];     // mean of neighbors
__device__ unsigned int g_galo[N_NODES * 64];
__device__ unsigned int g_Ah[2][N_NODES * 64];    // hin ping-pong (x -> buf 0)
__device__ unsigned int g_Al[2][N_NODES * 64];
__device__ unsigned int g_Bhi[W_ELEMS];           // per-layer B^T: [n 128][k2 128]
__device__ unsigned int g_Blo[W_ELEMS];

// ---------------- helpers ----------------
__device__ __forceinline__ uint32_t smem_u32(const void* p) {
    uint32_t a;
    asm("{ .reg .u64 t; cvta.to.shared.u64 t, %1; cvt.u32.u64 %0, t; }"
        : "=r"(a) : "l"(p));
    return a;
}
__device__ __forceinline__ void f16split2(float2 f, unsigned int& hi, unsigned int& lo) {
    __half2 h = __float22half2_rn(f);
    hi = *reinterpret_cast<unsigned int*>(&h);
    float2 hf = __half22float2(h);
    __half2 l = __float22half2_rn(make_float2(f.x - hf.x, f.y - hf.y));
    lo = *reinterpret_cast<unsigned int*>(&l);
}
__device__ __forceinline__ void acc_u2(float4& acc, uint2 u) {
    float2 f0 = __half22float2(*reinterpret_cast<__half2*>(&u.x));
    float2 f1 = __half22float2(*reinterpret_cast<__half2*>(&u.y));
    acc.x += f0.x; acc.y += f0.y; acc.z += f1.x; acc.w += f1.y;
}

#define CP_ASYNC16(dst, src, bytes) \
    asm volatile("cp.async.cg.shared.global [%0], [%1], 16, %2;" \
                 :: "r"(dst), "l"(src), "r"(bytes))
#define CP_COMMIT() asm volatile("cp.async.commit_group;" ::: "memory")
#define CP_WAIT1()  asm volatile("cp.async.wait_group 1;" ::: "memory")
#define CP_WAIT0()  asm volatile("cp.async.wait_group 0;" ::: "memory")

#define LDSM4(r, addr)                                                       \
    asm volatile("ldmatrix.sync.aligned.m8n8.x4.shared.b16 {%0,%1,%2,%3}, [%4];" \
                 : "=r"((r)[0]), "=r"((r)[1]), "=r"((r)[2]), "=r"((r)[3])    \
                 : "r"(addr))

#define MMA_F16(d, a, b0, b1)                                               \
    asm volatile("mma.sync.aligned.m16n8k16.row.col.f32.f16.f16.f32 "       \
                 "{%0,%1,%2,%3}, {%4,%5,%6,%7}, {%8,%9}, {%0,%1,%2,%3};"    \
                 : "+f"(d[0]), "+f"(d[1]), "+f"(d[2]), "+f"(d[3])           \
                 : "r"((a)[0]), "r"((a)[1]), "r"((a)[2]), "r"((a)[3]),      \
                   "r"(b0), "r"(b1))

// ---------------- utility ----------------
__global__ void zero_i(int* __restrict__ p, int n) {
    int i = blockIdx.x * blockDim.x + threadIdx.x;
    if (i < n) p[i] = 0;
}
__global__ void count_kernel(const int* __restrict__ dst, int nE) {
    int i = blockIdx.x * blockDim.x + threadIdx.x;
    if (i < nE) atomicAdd(&g_deg[dst[i]], 1);
}

// ---------------- parallel 3-phase scan over degrees ----------------
__global__ __launch_bounds__(256) void scan_blocksum() {
    __shared__ int red[256];
    int t = threadIdx.x;
    int i = blockIdx.x * 256 + t;
    int v = (i < N_NODES) ? g_deg[i] : 0;
    red[t] = v;
    __syncthreads();
    for (int off = 128; off > 0; off >>= 1) {
        if (t < off) red[t] += red[t + off];
        __syncthreads();
    }
    if (t == 0) g_blocksum[blockIdx.x] = red[0];
}
__global__ __launch_bounds__(256) void scan_top() {
    __shared__ int s[256];
    int t = threadIdx.x;
    int v = (t < SCAN_BLOCKS) ? g_blocksum[t] : 0;
    s[t] = v;
    __syncthreads();
    for (int off = 1; off < 256; off <<= 1) {
        int u = (t >= off) ? s[t - off] : 0;
        __syncthreads();
        s[t] += u;
        __syncthreads();
    }
    if (t < SCAN_BLOCKS) g_blockoff[t] = s[t] - v;   // exclusive
}
__global__ __launch_bounds__(256) void scan_low(int nE) {
    __shared__ int s[256];
    int t = threadIdx.x;
    int i = blockIdx.x * 256 + t;
    int v = (i < N_NODES) ? g_deg[i] : 0;
    s[t] = v;
    __syncthreads();
    for (int off = 1; off < 256; off <<= 1) {
        int u = (t >= off) ? s[t - off] : 0;
        __syncthreads();
        s[t] += u;
        __syncthreads();
    }
    if (i < N_NODES) {
        int excl = g_blockoff[blockIdx.x] + s[t] - v;
        g_rowstart[i] = excl;
        g_cursor[i] = excl;
        if (i == N_NODES - 1) g_rowstart[N_NODES] = nE;
    }
}

__global__ void fill_kernel(const int* __restrict__ src,
                            const int* __restrict__ dst, int nE) {
    int i = blockIdx.x * blockDim.x + threadIdx.x;
    if (i < nE) {
        int pos = atomicAdd(&g_cursor[dst[i]], 1);
        g_csr[pos] = src[i];
    }
}

// ---------------- split: weights B^T (hi/lo) + x (hi/lo) ----------------
// g_Bhi[L][n][k2] holds (B[2*k2][n], B[2*k2+1][n]) as fp16x2; B = fused [Wl;Wr].
__global__ void split_kernel(const float* __restrict__ Wl,
                             const float* __restrict__ Wr,
                             const float* __restrict__ x) {
    int i = blockIdx.x * blockDim.x + threadIdx.x;
    if (i < W_ELEMS) {
        int L = i >> 14;
        int r = i & 16383;
        int n = r >> 7;
        int k2 = r & 127;
        int k = k2 << 1;          // even; k and k+1 in the same matrix
        const float* W = (k < 128) ? (Wl + L * 16384 + k * 128)
                                   : (Wr + L * 16384 + (k - 128) * 128);
        unsigned int hi, lo;
        f16split2(make_float2(W[n], W[128 + n]), hi, lo);
        g_Bhi[i] = hi;
        g_Blo[i] = lo;
        return;
    }
    int j = i - W_ELEMS;
    if (j >= N_NODES * 64) return;
    int row = j >> 6;
    int n2 = j & 63;
    float2 v = *reinterpret_cast<const float2*>(x + (size_t)row * HID + 2 * n2);
    unsigned int hi, lo;
    f16split2(v, hi, lo);
    g_Ah[0][j] = hi;
    g_Al[0][j] = lo;
}

// ---------------- gather: warp per node, fp16-hi input, fp16 hi/lo output ----------------
__global__ __launch_bounds__(256) void gather_kernel(const unsigned int* __restrict__ h16) {
    int node = blockIdx.x * 8 + (threadIdx.x >> 5);
    if (node >= N_NODES) return;
    int lane = threadIdx.x & 31;
    int s0 = g_rowstart[node];
    int s1 = g_rowstart[node + 1];
    float4 acc = make_float4(0.f, 0.f, 0.f, 0.f);
    int j = s0;
    for (; j + 8 <= s1; j += 8) {
        int idx[8];
#pragma unroll
        for (int q = 0; q < 8; q++) idx[q] = __ldg(&g_csr[j + q]);
        uint2 v[8];
#pragma unroll
        for (int q = 0; q < 8; q++)
            v[q] = *reinterpret_cast<const uint2*>(h16 + (size_t)idx[q] * 64 + lane * 2);
#pragma unroll
        for (int q = 0; q < 8; q++) acc_u2(acc, v[q]);
    }
    for (; j < s1; j++) {
        uint2 a = *reinterpret_cast<const uint2*>(
            h16 + (size_t)__ldg(&g_csr[j]) * 64 + lane * 2);
        acc_u2(acc, a);
    }
    int deg = s1 - s0;
    float inv = 1.0f / (float)(deg > 0 ? deg : 1);
    acc.x *= inv; acc.y *= inv; acc.z *= inv; acc.w *= inv;
    unsigned int h0, l0, h1, l1;
    f16split2(make_float2(acc.x, acc.y), h0, l0);
    f16split2(make_float2(acc.z, acc.w), h1, l1);
    *reinterpret_cast<uint2*>(g_gahi + (size_t)node * 64 + lane * 2) = make_uint2(h0, h1);
    *reinterpret_cast<uint2*>(g_galo + (size_t)node * 64 + lane * 2) = make_uint2(l0, l1);
}

// ---------------- half-GEMM: K=128, 3-pass fp16, cp.async + ldmatrix ----------------
// MODE 0 (WR): tmp[m,n]  = hin[m,:] @ Wr-part of B            (A = Ah/Al args)
// MODE 1 (WL): out[m,n]  = relu(mean[m,:] @ Wl-part + tmp + bl) (A = g_gahi/galo)
template <int MODE>
__global__ __launch_bounds__(256) void sage_half_kernel(
    const unsigned int* __restrict__ Ah,     // used in MODE 0
    const unsigned int* __restrict__ Al,
    const unsigned int* __restrict__ Bhi,    // layer base, B^T [n 128][k2 128]
    const unsigned int* __restrict__ Blo,
    const float* __restrict__ bl,
    float* __restrict__ hout,                // fp32 out (MODE 1, if writeF32)
    unsigned int* __restrict__ Ohi,          // next-layer hin hi (MODE 1, if writeBf)
    unsigned int* __restrict__ Olo,
    int writeBf, int writeF32)
{
    extern __shared__ unsigned char dynsmem[];
    const uint32_t sbase = smem_u32(dynsmem);

    const int tid = threadIdx.x;
    const int lane = tid & 31;
    const int wid = tid >> 5;
    const int m0w = (wid >> 1) * 32;
    const int n0w = (wid & 1) * 64;
    const int rowBase = blockIdx.x * 128;
    const int grp = lane >> 2;
    const int tig = lane & 3;
    const int kbase = (MODE == 0) ? 64 : 0;   // k2 offset into B^T rows

    const int a_row_off = (lane & 7) + ((lane >> 3) & 1) * 8;
    const int a_k_off   = (lane >> 4) * 4;
    const int b_row_off = (lane & 7) + (lane >> 4) * 8;
    const int b_k_off   = ((lane >> 3) & 1) * 4;

    int arow[2], ac4[2];
#pragma unroll
    for (int i = 0; i < 2; i++) {
        int idx = tid + i * 256;
        arow[i] = idx >> 2;
        ac4[i] = (idx & 3) << 2;
    }

    float acc[2][8][4];
#pragma unroll
    for (int mt = 0; mt < 2; mt++)
#pragma unroll
        for (int nt = 0; nt < 8; nt++)
#pragma unroll
            for (int q = 0; q < 4; q++) acc[mt][nt][q] = 0.0f;

    auto issue = [&](int c, int buf) {
        const uint32_t sb = sbase + buf * SM_BUF;
        const unsigned int* srcHi = (MODE == 0) ? Ah : g_gahi;
        const unsigned int* srcLo = (MODE == 0) ? Al : g_galo;
        const int colBase = c * 16;
#pragma unroll
        for (int i = 0; i < 2; i++) {
            const unsigned int* bgh = Bhi + arow[i] * 128 + kbase + c * 16 + ac4[i];
            const unsigned int* bgl = Blo + arow[i] * 128 + kbase + c * 16 + ac4[i];
            CP_ASYNC16(sb + SM_BHI + (arow[i] * B_PITCH + ac4[i]) * 4, bgh, 16);
            CP_ASYNC16(sb + SM_BLO + (arow[i] * B_PITCH + ac4[i]) * 4, bgl, 16);
            int gm = rowBase + arow[i];
            int valid = (gm < N_NODES) ? 16 : 0;
            const unsigned int* agh = srcHi + (size_t)gm * 64 + colBase + ac4[i];
            const unsigned int* agl = srcLo + (size_t)gm * 64 + colBase + ac4[i];
            CP_ASYNC16(sb + SM_AHI + (arow[i] * A_PITCH + ac4[i]) * 4, agh, valid);
            CP_ASYNC16(sb + SM_ALO + (arow[i] * A_PITCH + ac4[i]) * 4, agl, valid);
        }
        CP_COMMIT();
    };

    issue(0, 0);

    for (int c = 0; c < 4; c++) {
        const int buf = c & 1;
        if (c < 3) { issue(c + 1, buf ^ 1); CP_WAIT1(); }
        else CP_WAIT0();
        __syncthreads();

        const uint32_t sb = sbase + buf * SM_BUF;

#pragma unroll
        for (int ks = 0; ks < 2; ks++) {
            const int k2b = ks * 8;
            unsigned int ahi[2][4], alo[2][4];
#pragma unroll
            for (int mt = 0; mt < 2; mt++) {
                uint32_t aaddr = sb + SM_AHI +
                    ((m0w + mt * 16 + a_row_off) * A_PITCH + k2b + a_k_off) * 4;
                LDSM4(ahi[mt], aaddr);
                LDSM4(alo[mt], aaddr + (SM_ALO - SM_AHI));
            }
#pragma unroll
            for (int p = 0; p < 4; p++) {
                unsigned int bh[4], blw[4];
                uint32_t baddr = sb + SM_BHI +
                    ((n0w + p * 16 + b_row_off) * B_PITCH + k2b + b_k_off) * 4;
                LDSM4(bh, baddr);
                LDSM4(blw, baddr + (SM_BLO - SM_BHI));
#pragma unroll
                for (int t = 0; t < 2; t++) {
                    const int nt = p * 2 + t;
#pragma unroll
                    for (int mt = 0; mt < 2; mt++) {
                        MMA_F16(acc[mt][nt], ahi[mt], bh[2 * t], bh[2 * t + 1]);
                        MMA_F16(acc[mt][nt], alo[mt], bh[2 * t], bh[2 * t + 1]);
                        MMA_F16(acc[mt][nt], ahi[mt], blw[2 * t], blw[2 * t + 1]);
                    }
                }
            }
        }
        __syncthreads();
    }

    // --- epilogue ---
#pragma unroll
    for (int mt = 0; mt < 2; mt++) {
        int gm0 = rowBase + m0w + mt * 16 + grp;
        int gm1 = gm0 + 8;
#pragma unroll
        for (int nt = 0; nt < 8; nt++) {
            int n = n0w + nt * 8 + 2 * tig;
            if (MODE == 0) {
                if (gm0 < N_NODES) {
                    float2 o = make_float2(acc[mt][nt][0], acc[mt][nt][1]);
                    *reinterpret_cast<float2*>(g_tmp + (size_t)gm0 * HID + n) = o;
                }
                if (gm1 < N_NODES) {
                    float2 o = make_float2(acc[mt][nt][2], acc[mt][nt][3]);
                    *reinterpret_cast<float2*>(g_tmp + (size_t)gm1 * HID + n) = o;
                }
            } else {
                float2 bb = *reinterpret_cast<const float2*>(bl + n);
                if (gm0 < N_NODES) {
                    float2 t = *reinterpret_cast<const float2*>(g_tmp + (size_t)gm0 * HID + n);
                    float2 o;
                    o.x = fmaxf(acc[mt][nt][0] + t.x + bb.x, 0.0f);
                    o.y = fmaxf(acc[mt][nt][1] + t.y + bb.y, 0.0f);
                    if (writeF32)
                        *reinterpret_cast<float2*>(hout + (size_t)gm0 * HID + n) = o;
                    if (writeBf) {
                        unsigned int hi, lo;
                        f16split2(o, hi, lo);
                        Ohi[(size_t)gm0 * 64 + (n >> 1)] = hi;
                        Olo[(size_t)gm0 * 64 + (n >> 1)] = lo;
                    }
                }
                if (gm1 < N_NODES) {
                    float2 t = *reinterpret_cast<const float2*>(g_tmp + (size_t)gm1 * HID + n);
                    float2 o;
                    o.x = fmaxf(acc[mt][nt][2] + t.x + bb.x, 0.0f);
                    o.y = fmaxf(acc[mt][nt][3] + t.y + bb.y, 0.0f);
                    if (writeF32)
                        *reinterpret_cast<float2*>(hout + (size_t)gm1 * HID + n) = o;
                    if (writeBf) {
                        unsigned int hi, lo;
                        f16split2(o, hi, lo);
                        Ohi[(size_t)gm1 * 64 + (n >> 1)] = hi;
                        Olo[(size_t)gm1 * 64 + (n >> 1)] = lo;
                    }
                }
            }
        }
    }
}

// ---------------- pool: one block per graph, atomic-free (batch sorted) ----------------
__global__ __launch_bounds__(128) void pool_kernel(
    const float* __restrict__ hin, const int* __restrict__ batch)
{
    int g = blockIdx.x;
    int c = threadIdx.x;
    int lo = 0, hi = N_NODES;
    while (lo < hi) { int mid = (lo + hi) >> 1; if (__ldg(&batch[mid]) < g) lo = mid + 1; else hi = mid; }
    int start = lo;
    hi = N_NODES;
    while (lo < hi) { int mid = (lo + hi) >> 1; if (__ldg(&batch[mid]) <= g) lo = mid + 1; else hi = mid; }
    int end = lo;
    float acc = 0.0f;
    for (int r = start; r < end; r++)
        acc += hin[(size_t)r * HID + c];
    g_pooled[g * HID + c] = acc;
}

// ---------------- batchnorm stats ----------------
__global__ __launch_bounds__(128) void bn_kernel(
    const float* __restrict__ gamma, const float* __restrict__ beta)
{
    int c = threadIdx.x;
    float s = 0.0f, s2 = 0.0f;
    for (int g = 0; g < N_GRAPHS; g++) {
        float v = g_pooled[g * HID + c];
        s += v;
        s2 += v * v;
    }
    float mu = s * (1.0f / N_GRAPHS);
    float var = s2 * (1.0f / N_GRAPHS) - mu * mu;
    float sc = gamma[c] * rsqrtf(var + BN_EPS);
    g_scale[c] = sc;
    g_shift[c] = beta[c] - mu * sc;
}

// ---------------- final FC ----------------
__global__ __launch_bounds__(64) void final_kernel(
    const float* __restrict__ fcW, const float* __restrict__ fcb,
    float* __restrict__ out)
{
    __shared__ float row[HID];
    int g = blockIdx.x;
    int l = threadIdx.x;
    for (int c = l; c < HID; c += 64)
        row[c] = g_pooled[g * HID + c] * g_scale[c] + g_shift[c];
    __syncthreads();
    float acc = fcb[l];
#pragma unroll
    for (int c = 0; c < HID; c++)
        acc += row[c] * __ldg(&fcW[c * LATENT + l]);
    out[g * LATENT + l] = acc;
}

// ---------------- launch ----------------
extern "C" void kernel_launch(void* const* d_in, const int* in_sizes, int n_in,
                              void* d_out, int out_size)
{
    const float* x     = (const float*)d_in[0];
    const int*   ei    = (const int*)d_in[1];
    const int*   batch = (const int*)d_in[2];
    const float* Wl    = (const float*)d_in[3];
    const float* bl    = (const float*)d_in[4];
    const float* Wr    = (const float*)d_in[5];
    const float* gamma = (const float*)d_in[6];
    const float* beta  = (const float*)d_in[7];
    const float* fcW   = (const float*)d_in[8];
    const float* fcb   = (const float*)d_in[9];
    float* out = (float*)d_out;

    const int E = in_sizes[1] / 2;
    const int* src = ei;
    const int* dst = ei + E;

    float *hf32;
    int *deg;
    unsigned int *bhi, *blo, *ah, *al;
    cudaGetSymbolAddress((void**)&hf32, g_hf32);
    cudaGetSymbolAddress((void**)&deg, g_deg);
    cudaGetSymbolAddress((void**)&bhi, g_Bhi);
    cudaGetSymbolAddress((void**)&blo, g_Blo);
    cudaGetSymbolAddress((void**)&ah, g_Ah);
    cudaGetSymbolAddress((void**)&al, g_Al);

    cudaFuncSetAttribute(sage_half_kernel<0>,
                         cudaFuncAttributeMaxDynamicSharedMemorySize, SM_TOTAL);
    cudaFuncSetAttribute(sage_half_kernel<1>,
                         cudaFuncAttributeMaxDynamicSharedMemorySize, SM_TOTAL);

    // streams/events: created ONCE on the first (eager) call, reused under capture.
    static cudaStream_t s2 = nullptr;
    static cudaEvent_t ev[8];
    static bool inited = false;
    if (!inited) {
        if (cudaStreamCreateWithFlags(&s2, cudaStreamNonBlocking) != cudaSuccess)
            s2 = nullptr;
        for (int i = 0; i < 8; i++)
            cudaEventCreateWithFlags(&ev[i], cudaEventDisableTiming);
        inited = true;
    }
    cudaStream_t S0 = (cudaStream_t)0;
    cudaStream_t SB = s2 ? s2 : S0;

    // ---- fork: operand split on SB, CSR build on S0 ----
    cudaEventRecord(ev[0], S0);
    cudaStreamWaitEvent(SB, ev[0], 0);
    split_kernel<<<(W_ELEMS + N_NODES * 64 + 255) / 256, 256, 0, SB>>>(Wl, Wr, x);
    cudaEventRecord(ev[1], SB);

    zero_i<<<(N_NODES + 255) / 256, 256, 0, S0>>>(deg, N_NODES);
    count_kernel<<<(E + 255) / 256, 256, 0, S0>>>(dst, E);
    scan_blocksum<<<SCAN_BLOCKS, 256, 0, S0>>>();
    scan_top<<<1, 256, 0, S0>>>();
    scan_low<<<SCAN_BLOCKS, 256, 0, S0>>>(E);
    fill_kernel<<<(E + 255) / 256, 256, 0, S0>>>(src, dst, E);
    cudaStreamWaitEvent(S0, ev[1], 0);   // join split

    for (int layer = 0; layer < 3; layer++) {
        int cur = layer & 1;
        int nxt = cur ^ 1;
        unsigned int* Ahc = ah + cur * (N_NODES * 64);
        unsigned int* Alc = al + cur * (N_NODES * 64);

        // fork: wr half-GEMM (tensor-bound) on SB || gather (L2-bound) on S0
        cudaEventRecord(ev[2 + layer * 2], S0);
        cudaStreamWaitEvent(SB, ev[2 + layer * 2], 0);
        sage_half_kernel<0><<<GEMM_BLOCKS, 256, SM_TOTAL, SB>>>(
            Ahc, Alc, bhi + layer * 16384, blo + layer * 16384,
            nullptr, nullptr, nullptr, nullptr, 0, 0);
        cudaEventRecord(ev[3 + layer * 2], SB);

        gather_kernel<<<(N_NODES + 7) / 8, 256, 0, S0>>>(Ahc);
        cudaStreamWaitEvent(S0, ev[3 + layer * 2], 0);   // join wr

        sage_half_kernel<1><<<GEMM_BLOCKS, 256, SM_TOTAL, S0>>>(
            nullptr, nullptr, bhi + layer * 16384, blo + layer * 16384,
            bl + layer * HID, hf32,
            ah + nxt * (N_NODES * 64), al + nxt * (N_NODES * 64),
            (layer < 2) ? 1 : 0, (layer == 2) ? 1 : 0);
    }

    pool_kernel<<<N_GRAPHS, 128, 0, S0>>>(hf32, batch);
    bn_kernel<<<1, 128, 0, S0>>>(gamma, beta);
    final_kernel<<<N_GRAPHS, 64, 0, S0>>>(fcW, fcb, out);
}

// round 15
// speedup vs baseline: 1.3641x; 1.3641x over previous
#include <cuda_runtime.h>
#include <cuda_fp16.h>
#include <cstdint>

#define N_NODES 50000
#define HID 128
#define LATENT 64
#define N_GRAPHS 256
#define BN_EPS 1e-5f
#define SCAN_BLOCKS 196          // 196*256 >= 50000
#define GEMM_BLOCKS 391          // ceil(50000/128)

#define A_PITCH 20               // uints per A smem row -> ldmatrix conflict-free
#define B_PITCH 20               // uints per B^T smem row -> ldmatrix conflict-free

// dynamic smem layout per buffer (bytes)
#define SM_AHI 0
#define SM_ALO 10240             // 128*20*4
#define SM_BHI 20480
#define SM_BLO 30720
#define SM_BUF 40960
#define SM_TOTAL (2 * SM_BUF)

#define W_ELEMS (3 * 128 * 128)  // fused weight image elements (uint-packed, B^T [n][k2])

// ---------------- device scratch (static, no allocation) ----------------
__device__ float g_hf32[N_NODES * HID];           // fp32 h (layer 2 only, for pool)
__device__ int   g_deg[N_NODES];
__device__ int   g_rowstart[N_NODES + 1];
__device__ int   g_cursor[N_NODES];
__device__ int   g_csr[800000 * 2];
__device__ int   g_blocksum[SCAN_BLOCKS];
__device__ float g_pooled[N_GRAPHS * HID];
__device__ float g_scale[HID];
__device__ float g_shift[HID];
// fp16x2-packed hi/lo images (64 uints per 128-ch row)
__device__ unsigned int g_gahi[N_NODES * 64];     // mean of neighbors
__device__ unsigned int g_galo[N_NODES * 64];
__device__ unsigned int g_Ah[2][N_NODES * 64];    // hin ping-pong (x -> buf 0)
__device__ unsigned int g_Al[2][N_NODES * 64];
__device__ unsigned int g_Bhi[W_ELEMS];           // per-layer B^T: [n 128][k2 128]
__device__ unsigned int g_Blo[W_ELEMS];

// ---------------- helpers ----------------
__device__ __forceinline__ uint32_t smem_u32(const void* p) {
    uint32_t a;
    asm("{ .reg .u64 t; cvta.to.shared.u64 t, %1; cvt.u32.u64 %0, t; }"
        : "=r"(a) : "l"(p));
    return a;
}
__device__ __forceinline__ void f16split2(float2 f, unsigned int& hi, unsigned int& lo) {
    __half2 h = __float22half2_rn(f);
    hi = *reinterpret_cast<unsigned int*>(&h);
    float2 hf = __half22float2(h);
    __half2 l = __float22half2_rn(make_float2(f.x - hf.x, f.y - hf.y));
    lo = *reinterpret_cast<unsigned int*>(&l);
}
__device__ __forceinline__ void acc_u2(float4& acc, uint2 u) {
    float2 f0 = __half22float2(*reinterpret_cast<__half2*>(&u.x));
    float2 f1 = __half22float2(*reinterpret_cast<__half2*>(&u.y));
    acc.x += f0.x; acc.y += f0.y; acc.z += f1.x; acc.w += f1.y;
}

#define CP_ASYNC16(dst, src, bytes) \
    asm volatile("cp.async.cg.shared.global [%0], [%1], 16, %2;" \
                 :: "r"(dst), "l"(src), "r"(bytes))
#define CP_COMMIT() asm volatile("cp.async.commit_group;" ::: "memory")
#define CP_WAIT1()  asm volatile("cp.async.wait_group 1;" ::: "memory")
#define CP_WAIT0()  asm volatile("cp.async.wait_group 0;" ::: "memory")

#define LDSM4(r, addr)                                                       \
    asm volatile("ldmatrix.sync.aligned.m8n8.x4.shared.b16 {%0,%1,%2,%3}, [%4];" \
                 : "=r"((r)[0]), "=r"((r)[1]), "=r"((r)[2]), "=r"((r)[3])    \
                 : "r"(addr))

#define MMA_F16(d, a, b0, b1)                                               \
    asm volatile("mma.sync.aligned.m16n8k16.row.col.f32.f16.f16.f32 "       \
                 "{%0,%1,%2,%3}, {%4,%5,%6,%7}, {%8,%9}, {%0,%1,%2,%3};"    \
                 : "+f"(d[0]), "+f"(d[1]), "+f"(d[2]), "+f"(d[3])           \
                 : "r"((a)[0]), "r"((a)[1]), "r"((a)[2]), "r"((a)[3]),      \
                   "r"(b0), "r"(b1))

// ---------------- utility ----------------
__global__ void zero_i(int* __restrict__ p, int n) {
    int i = blockIdx.x * blockDim.x + threadIdx.x;
    if (i < n) p[i] = 0;
}
__global__ void count_kernel(const int* __restrict__ dst, int nE) {
    int i = blockIdx.x * blockDim.x + threadIdx.x;
    if (i < nE) atomicAdd(&g_deg[dst[i]], 1);
}

// ---------------- scan: per-chunk reduction, then fused (top + low) scan ----------------
__global__ __launch_bounds__(256) void scan_blocksum() {
    __shared__ int red[256];
    int t = threadIdx.x;
    int i = blockIdx.x * 256 + t;
    int v = (i < N_NODES) ? g_deg[i] : 0;
    red[t] = v;
    __syncthreads();
    for (int off = 128; off > 0; off >>= 1) {
        if (t < off) red[t] += red[t + off];
        __syncthreads();
    }
    if (t == 0) g_blocksum[blockIdx.x] = red[0];
}
// each block redundantly scans the 196 blocksums (smem), then scans its own chunk
__global__ __launch_bounds__(256) void scan_low_fused(int nE) {
    __shared__ int s_a[256];
    __shared__ int s_b[256];
    int t = threadIdx.x;
    int v = (t < SCAN_BLOCKS) ? g_blocksum[t] : 0;
    s_b[t] = v;
    __syncthreads();
    for (int off = 1; off < 256; off <<= 1) {
        int u = (t >= off) ? s_b[t - off] : 0;
        __syncthreads();
        s_b[t] += u;
        __syncthreads();
    }
    const int chunk = blockIdx.x;
    const int chunkBase = s_b[chunk] - g_blocksum[chunk];   // exclusive base
    int i = chunk * 256 + t;
    int v2 = (i < N_NODES) ? g_deg[i] : 0;
    s_a[t] = v2;
    __syncthreads();
    for (int off = 1; off < 256; off <<= 1) {
        int u = (t >= off) ? s_a[t - off] : 0;
        __syncthreads();
        s_a[t] += u;
        __syncthreads();
    }
    if (i < N_NODES) {
        int excl = chunkBase + s_a[t] - v2;
        g_rowstart[i] = excl;
        g_cursor[i] = excl;
        if (i == N_NODES - 1) g_rowstart[N_NODES] = nE;
    }
}

__global__ void fill_kernel(const int* __restrict__ src,
                            const int* __restrict__ dst, int nE) {
    int i = blockIdx.x * blockDim.x + threadIdx.x;
    if (i < nE) {
        int pos = atomicAdd(&g_cursor[dst[i]], 1);
        g_csr[pos] = src[i];
    }
}

// ---------------- split: weights B^T (hi/lo) + x (hi/lo), single launch ----------------
// g_Bhi[L][n][k2] holds (B[2*k2][n], B[2*k2+1][n]) as fp16x2; B = fused [Wl;Wr].
__global__ void split_kernel(const float* __restrict__ Wl,
                             const float* __restrict__ Wr,
                             const float* __restrict__ x) {
    int i = blockIdx.x * blockDim.x + threadIdx.x;
    if (i < W_ELEMS) {
        int L = i >> 14;
        int r = i & 16383;
        int n = r >> 7;
        int k2 = r & 127;
        int k = k2 << 1;          // even; k and k+1 in the same matrix
        const float* W = (k < 128) ? (Wl + L * 16384 + k * 128)
                                   : (Wr + L * 16384 + (k - 128) * 128);
        unsigned int hi, lo;
        f16split2(make_float2(W[n], W[128 + n]), hi, lo);
        g_Bhi[i] = hi;
        g_Blo[i] = lo;
        return;
    }
    int j = i - W_ELEMS;
    if (j >= N_NODES * 64) return;
    int row = j >> 6;
    int n2 = j & 63;
    float2 v = *reinterpret_cast<const float2*>(x + (size_t)row * HID + 2 * n2);
    unsigned int hi, lo;
    f16split2(v, hi, lo);
    g_Ah[0][j] = hi;
    g_Al[0][j] = lo;
}

// ---------------- gather: warp per node, fp16-hi input, fp16 hi/lo output ----------------
__global__ __launch_bounds__(256) void gather_kernel(const unsigned int* __restrict__ h16) {
    int node = blockIdx.x * 8 + (threadIdx.x >> 5);
    if (node >= N_NODES) return;
    int lane = threadIdx.x & 31;
    int s0 = g_rowstart[node];
    int s1 = g_rowstart[node + 1];
    float4 acc = make_float4(0.f, 0.f, 0.f, 0.f);
    int j = s0;
    for (; j + 8 <= s1; j += 8) {
        int idx[8];
#pragma unroll
        for (int q = 0; q < 8; q++) idx[q] = __ldg(&g_csr[j + q]);
        uint2 v[8];
#pragma unroll
        for (int q = 0; q < 8; q++)
            v[q] = *reinterpret_cast<const uint2*>(h16 + (size_t)idx[q] * 64 + lane * 2);
#pragma unroll
        for (int q = 0; q < 8; q++) acc_u2(acc, v[q]);
    }
    for (; j < s1; j++) {
        uint2 a = *reinterpret_cast<const uint2*>(
            h16 + (size_t)__ldg(&g_csr[j]) * 64 + lane * 2);
        acc_u2(acc, a);
    }
    int deg = s1 - s0;
    float inv = 1.0f / (float)(deg > 0 ? deg : 1);
    acc.x *= inv; acc.y *= inv; acc.z *= inv; acc.w *= inv;
    unsigned int h0, l0, h1, l1;
    f16split2(make_float2(acc.x, acc.y), h0, l0);
    f16split2(make_float2(acc.z, acc.w), h1, l1);
    *reinterpret_cast<uint2*>(g_gahi + (size_t)node * 64 + lane * 2) = make_uint2(h0, h1);
    *reinterpret_cast<uint2*>(g_galo + (size_t)node * 64 + lane * 2) = make_uint2(l0, l1);
}

// ---------------- fp16 3-pass MMA GEMM, cp.async double-buffered + ldmatrix ----------------
// hout[m,n] = relu( [agg|hin][m,:] @ (Bhi+Blo) + bl[n] ),  K=256
// block 128x128, 8 warps (4m x 2n), warp tile 32x64, mma m16n8k16 f16.
__global__ __launch_bounds__(256) void sage_mma_kernel(
    const unsigned int* __restrict__ Ah,     // hin hi [N][64]
    const unsigned int* __restrict__ Al,     // hin lo
    const unsigned int* __restrict__ Bhi,    // B^T [128 n][128 k2] this layer
    const unsigned int* __restrict__ Blo,
    const float* __restrict__ bl,
    float* __restrict__ hout,                // fp32 out (if writeF32)
    unsigned int* __restrict__ Ohi,          // next-layer hin hi (if writeBf)
    unsigned int* __restrict__ Olo,
    int writeBf, int writeF32)
{
    extern __shared__ unsigned char dynsmem[];
    const uint32_t sbase = smem_u32(dynsmem);

    const int tid = threadIdx.x;
    const int lane = tid & 31;
    const int wid = tid >> 5;
    const int m0w = (wid >> 1) * 32;
    const int n0w = (wid & 1) * 64;
    const int rowBase = blockIdx.x * 128;
    const int grp = lane >> 2;   // 0..7
    const int tig = lane & 3;    // 0..3

    // ldmatrix lane address components
    const int a_row_off = (lane & 7) + ((lane >> 3) & 1) * 8;  // 0..15
    const int a_k_off   = (lane >> 4) * 4;                     // 0 or 4 (uints)
    const int b_row_off = (lane & 7) + (lane >> 4) * 8;        // 0..15
    const int b_k_off   = ((lane >> 3) & 1) * 4;               // 0 or 4 (uints)

    // per-thread copy slots (2 x uint4 each for A and B^T)
    int arow[2], ac4[2];
#pragma unroll
    for (int i = 0; i < 2; i++) {
        int idx = tid + i * 256;
        arow[i] = idx >> 2;           // 0..127
        ac4[i] = (idx & 3) << 2;      // 0,4,8,12
    }

    float acc[2][8][4];
#pragma unroll
    for (int mt = 0; mt < 2; mt++)
#pragma unroll
        for (int nt = 0; nt < 8; nt++)
#pragma unroll
            for (int q = 0; q < 4; q++) acc[mt][nt][q] = 0.0f;

    // chunk issue: c = 0..7 (0-3 agg, 4-7 hin), buf = target buffer
    auto issue = [&](int c, int buf) {
        const uint32_t sb = sbase + buf * SM_BUF;
        const unsigned int* srcHi = (c < 4) ? g_gahi : Ah;
        const unsigned int* srcLo = (c < 4) ? g_galo : Al;
        const int colBase = (c & 3) * 16;
#pragma unroll
        for (int i = 0; i < 2; i++) {
            // B^T chunk: row = n (0..127), 16 uints of k2 starting at c*16
            const unsigned int* bgh = Bhi + arow[i] * 128 + c * 16 + ac4[i];
            const unsigned int* bgl = Blo + arow[i] * 128 + c * 16 + ac4[i];
            CP_ASYNC16(sb + SM_BHI + (arow[i] * B_PITCH + ac4[i]) * 4, bgh, 16);
            CP_ASYNC16(sb + SM_BLO + (arow[i] * B_PITCH + ac4[i]) * 4, bgl, 16);
            // A chunk
            int gm = rowBase + arow[i];
            int valid = (gm < N_NODES) ? 16 : 0;
            const unsigned int* agh = srcHi + (size_t)gm * 64 + colBase + ac4[i];
            const unsigned int* agl = srcLo + (size_t)gm * 64 + colBase + ac4[i];
            CP_ASYNC16(sb + SM_AHI + (arow[i] * A_PITCH + ac4[i]) * 4, agh, valid);
            CP_ASYNC16(sb + SM_ALO + (arow[i] * A_PITCH + ac4[i]) * 4, agl, valid);
        }
        CP_COMMIT();
    };

    issue(0, 0);

    for (int c = 0; c < 8; c++) {
        const int buf = c & 1;
        if (c < 7) { issue(c + 1, buf ^ 1); CP_WAIT1(); }
        else CP_WAIT0();
        __syncthreads();

        const uint32_t sb = sbase + buf * SM_BUF;

#pragma unroll
        for (int ks = 0; ks < 2; ks++) {
            const int k2b = ks * 8;
            unsigned int ahi[2][4], alo[2][4];
#pragma unroll
            for (int mt = 0; mt < 2; mt++) {
                uint32_t aaddr = sb + SM_AHI +
                    ((m0w + mt * 16 + a_row_off) * A_PITCH + k2b + a_k_off) * 4;
                LDSM4(ahi[mt], aaddr);
                LDSM4(alo[mt], aaddr + (SM_ALO - SM_AHI));
            }
#pragma unroll
            for (int p = 0; p < 4; p++) {
                unsigned int bh[4], blw[4];
                uint32_t baddr = sb + SM_BHI +
                    ((n0w + p * 16 + b_row_off) * B_PITCH + k2b + b_k_off) * 4;
                LDSM4(bh, baddr);
                LDSM4(blw, baddr + (SM_BLO - SM_BHI));
#pragma unroll
                for (int t = 0; t < 2; t++) {
                    const int nt = p * 2 + t;
#pragma unroll
                    for (int mt = 0; mt < 2; mt++) {
                        MMA_F16(acc[mt][nt], ahi[mt], bh[2 * t], bh[2 * t + 1]);
                        MMA_F16(acc[mt][nt], alo[mt], bh[2 * t], bh[2 * t + 1]);
                        MMA_F16(acc[mt][nt], ahi[mt], blw[2 * t], blw[2 * t + 1]);
                    }
                }
            }
        }
        __syncthreads();
    }

    // --- epilogue: +bias, relu; fp16 hi/lo store (layers 0,1) or fp32 (layer 2) ---
#pragma unroll
    for (int mt = 0; mt < 2; mt++) {
        int gm0 = rowBase + m0w + mt * 16 + grp;
        int gm1 = gm0 + 8;
#pragma unroll
        for (int nt = 0; nt < 8; nt++) {
            int n = n0w + nt * 8 + 2 * tig;
            float2 bb = *reinterpret_cast<const float2*>(bl + n);
            if (gm0 < N_NODES) {
                float2 o;
                o.x = fmaxf(acc[mt][nt][0] + bb.x, 0.0f);
                o.y = fmaxf(acc[mt][nt][1] + bb.y, 0.0f);
                if (writeF32)
                    *reinterpret_cast<float2*>(hout + (size_t)gm0 * HID + n) = o;
                if (writeBf) {
                    unsigned int hi, lo;
                    f16split2(o, hi, lo);
                    Ohi[(size_t)gm0 * 64 + (n >> 1)] = hi;
                    Olo[(size_t)gm0 * 64 + (n >> 1)] = lo;
                }
            }
            if (gm1 < N_NODES) {
                float2 o;
                o.x = fmaxf(acc[mt][nt][2] + bb.x, 0.0f);
                o.y = fmaxf(acc[mt][nt][3] + bb.y, 0.0f);
                if (writeF32)
                    *reinterpret_cast<float2*>(hout + (size_t)gm1 * HID + n) = o;
                if (writeBf) {
                    unsigned int hi, lo;
                    f16split2(o, hi, lo);
                    Ohi[(size_t)gm1 * 64 + (n >> 1)] = hi;
                    Olo[(size_t)gm1 * 64 + (n >> 1)] = lo;
                }
            }
        }
    }
}

// ---------------- pool: one block per graph, atomic-free (batch sorted) ----------------
__global__ __launch_bounds__(128) void pool_kernel(
    const float* __restrict__ hin, const int* __restrict__ batch)
{
    int g = blockIdx.x;
    int c = threadIdx.x;
    int lo = 0, hi = N_NODES;
    while (lo < hi) { int mid = (lo + hi) >> 1; if (__ldg(&batch[mid]) < g) lo = mid + 1; else hi = mid; }
    int start = lo;
    hi = N_NODES;
    while (lo < hi) { int mid = (lo + hi) >> 1; if (__ldg(&batch[mid]) <= g) lo = mid + 1; else hi = mid; }
    int end = lo;
    float acc = 0.0f;
    for (int r = start; r < end; r++)
        acc += hin[(size_t)r * HID + c];
    g_pooled[g * HID + c] = acc;
}

// ---------------- batchnorm stats ----------------
__global__ __launch_bounds__(128) void bn_kernel(
    const float* __restrict__ gamma, const float* __restrict__ beta)
{
    int c = threadIdx.x;
    float s = 0.0f, s2 = 0.0f;
    for (int g = 0; g < N_GRAPHS; g++) {
        float v = g_pooled[g * HID + c];
        s += v;
        s2 += v * v;
    }
    float mu = s * (1.0f / N_GRAPHS);
    float var = s2 * (1.0f / N_GRAPHS) - mu * mu;
    float sc = gamma[c] * rsqrtf(var + BN_EPS);
    g_scale[c] = sc;
    g_shift[c] = beta[c] - mu * sc;
}

// ---------------- final FC ----------------
__global__ __launch_bounds__(64) void final_kernel(
    const float* __restrict__ fcW, const float* __restrict__ fcb,
    float* __restrict__ out)
{
    __shared__ float row[HID];
    int g = blockIdx.x;
    int l = threadIdx.x;
    for (int c = l; c < HID; c += 64)
        row[c] = g_pooled[g * HID + c] * g_scale[c] + g_shift[c];
    __syncthreads();
    float acc = fcb[l];
#pragma unroll
    for (int c = 0; c < HID; c++)
        acc += row[c] * __ldg(&fcW[c * LATENT + l]);
    out[g * LATENT + l] = acc;
}

// ---------------- launch ----------------
extern "C" void kernel_launch(void* const* d_in, const int* in_sizes, int n_in,
                              void* d_out, int out_size)
{
    const float* x     = (const float*)d_in[0];
    const int*   ei    = (const int*)d_in[1];
    const int*   batch = (const int*)d_in[2];
    const float* Wl    = (const float*)d_in[3];
    const float* bl    = (const float*)d_in[4];
    const float* Wr    = (const float*)d_in[5];
    const float* gamma = (const float*)d_in[6];
    const float* beta  = (const float*)d_in[7];
    const float* fcW   = (const float*)d_in[8];
    const float* fcb   = (const float*)d_in[9];
    float* out = (float*)d_out;

    const int E = in_sizes[1] / 2;
    const int* src = ei;
    const int* dst = ei + E;

    float *hf32;
    int *deg;
    unsigned int *bhi, *blo, *ah, *al;
    cudaGetSymbolAddress((void**)&hf32, g_hf32);
    cudaGetSymbolAddress((void**)&deg, g_deg);
    cudaGetSymbolAddress((void**)&bhi, g_Bhi);
    cudaGetSymbolAddress((void**)&blo, g_Blo);
    cudaGetSymbolAddress((void**)&ah, g_Ah);
    cudaGetSymbolAddress((void**)&al, g_Al);

    cudaFuncSetAttribute(sage_mma_kernel,
                         cudaFuncAttributeMaxDynamicSharedMemorySize, SM_TOTAL);

    // streams/events: created ONCE on the first (eager) call, reused under capture.
    static cudaStream_t s2 = nullptr;
    static cudaEvent_t ev0, ev1;
    static bool inited = false;
    if (!inited) {
        if (cudaStreamCreateWithFlags(&s2, cudaStreamNonBlocking) != cudaSuccess)
            s2 = nullptr;
        cudaEventCreateWithFlags(&ev0, cudaEventDisableTiming);
        cudaEventCreateWithFlags(&ev1, cudaEventDisableTiming);
        inited = true;
    }
    cudaStream_t S0 = (cudaStream_t)0;

    // ---- fork: operand split on SB || CSR build on S0 ----
    if (s2) {
        cudaEventRecord(ev0, S0);
        cudaStreamWaitEvent(s2, ev0, 0);
        split_kernel<<<(W_ELEMS + N_NODES * 64 + 255) / 256, 256, 0, s2>>>(Wl, Wr, x);
        cudaEventRecord(ev1, s2);
    } else {
        split_kernel<<<(W_ELEMS + N_NODES * 64 + 255) / 256, 256, 0, S0>>>(Wl, Wr, x);
    }

    zero_i<<<(N_NODES + 255) / 256, 256, 0, S0>>>(deg, N_NODES);
    count_kernel<<<(E + 255) / 256, 256, 0, S0>>>(dst, E);
    scan_blocksum<<<SCAN_BLOCKS, 256, 0, S0>>>();
    scan_low_fused<<<SCAN_BLOCKS, 256, 0, S0>>>(E);
    fill_kernel<<<(E + 255) / 256, 256, 0, S0>>>(src, dst, E);
    if (s2) cudaStreamWaitEvent(S0, ev1, 0);   // join split

    for (int layer = 0; layer < 3; layer++) {
        int cur = layer & 1;          // hin fp16 buffer
        int nxt = cur ^ 1;
        gather_kernel<<<(N_NODES + 7) / 8, 256, 0, S0>>>(ah + cur * (N_NODES * 64));
        sage_mma_kernel<<<GEMM_BLOCKS, 256, SM_TOTAL, S0>>>(
            ah + cur * (N_NODES * 64), al + cur * (N_NODES * 64),
            bhi + layer * 16384, blo + layer * 16384,
            bl + layer * HID, hf32,
            ah + nxt * (N_NODES * 64), al + nxt * (N_NODES * 64),
            (layer < 2) ? 1 : 0, (layer == 2) ? 1 : 0);
    }

    pool_kernel<<<N_GRAPHS, 128, 0, S0>>>(hf32, batch);
    bn_kernel<<<1, 128, 0, S0>>>(gamma, beta);
    final_kernel<<<N_GRAPHS, 64, 0, S0>>>(fcW, fcb, out);
}